// round 3
// baseline (speedup 1.0000x reference)
#include <cuda_runtime.h>

// Batched 11-qubit PQC simulation — register-resident statevector,
// 2 batch elements per thread packed into f32x2 (FFMA2 SIMD over batch).
//
//  * CNOT(q->q+1) cascade == permutation new[x] = old[(x ^ (x<<1)) & 2047].
//  * Layer 1 on |0> is a tensor product -> closed-form init into registers.
//  * Layer 2: 11 commuting single-qubit gates applied where each bit lives:
//      qubits 8-10 : local (register) butterflies
//      qubits 0-4  : warp-shuffle butterflies
//      qubits 5-7  : one smem bit-swap (5-7 <-> 8-10), then register butterflies
//  * Final cascade fused into a re-only smem bounce + coalesced stores.

#define NQ       11
#define NL       2
#define SDIM     2048
#define NTHREADS 256

typedef unsigned long long u64;

__device__ __forceinline__ int graymap(int x) {
    return (x ^ (x << 1)) & (SDIM - 1);
}

__device__ __forceinline__ u64 fmul2(u64 a, u64 b) {
    u64 r; asm("mul.rn.f32x2 %0, %1, %2;" : "=l"(r) : "l"(a), "l"(b)); return r;
}
__device__ __forceinline__ u64 ffma2(u64 a, u64 b, u64 c) {
    u64 r; asm("fma.rn.f32x2 %0, %1, %2, %3;" : "=l"(r) : "l"(a), "l"(b), "l"(c)); return r;
}
__device__ __forceinline__ u64 fneg2(u64 a) {
    return a ^ 0x8000000080000000ULL;
}
__device__ __forceinline__ void unpk(u64 v, float& x, float& y) {
    asm("mov.b64 {%0, %1}, %2;" : "=f"(x), "=f"(y) : "l"(v));
}

__global__ __launch_bounds__(NTHREADS, 4)
void pqc_kernel(const float* __restrict__ theta,
                const int*   __restrict__ positions,
                float*       __restrict__ out)
{
    __shared__ u64 sre[SDIM];                    // 16 KB
    __shared__ u64 sim[SDIM];                    // 16 KB
    __shared__ __align__(8) float Ugf[NL * NQ][8][2];  // [gate][component][batch-half]

    const int b0   = blockIdx.x * 2;
    const int t    = threadIdx.x;
    const int lane = t & 31;
    const int w    = t >> 5;

    // ---- Gate matrices: U = Rz(g)*Ry(b)*Rx(a), half-angles; both halves ----
    if (t < 2 * NL * NQ) {
        const int g2 = t >> 1;                 // gate index 0..21
        const int h  = t & 1;                  // batch half
        const int l  = g2 / NQ, q = g2 - l * NQ;
        const int p  = positions[b0 + h];
        const float* th = theta + (long long)p * (NL * 3 * NQ) + l * 3 * NQ + q * 3;
        const float a  = 0.5f * th[0];
        const float bb = 0.5f * th[1];
        const float g  = 0.5f * th[2];
        float sa, ca, sb, cb, sg, cg;
        sincosf(a,  &sa, &ca);
        sincosf(bb, &sb, &cb);
        sincosf(g,  &sg, &cg);
        const float cbca = cb * ca, sbsa = sb * sa;
        const float sbca = sb * ca, cbsa = cb * sa;
        Ugf[g2][0][h] =  cg * cbca + sg * sbsa;   // u00.re
        Ugf[g2][1][h] =  cg * sbsa - sg * cbca;   // u00.im
        Ugf[g2][2][h] = -cg * sbca - sg * cbsa;   // u01.re
        Ugf[g2][3][h] = -cg * cbsa + sg * sbca;   // u01.im
        Ugf[g2][4][h] =  cg * sbca + sg * cbsa;   // u10.re
        Ugf[g2][5][h] =  sg * sbca - cg * cbsa;   // u10.im
        Ugf[g2][6][h] =  cg * cbca + sg * sbsa;   // u11.re
        Ugf[g2][7][h] =  sg * cbca - cg * sbsa;   // u11.im
    }
    __syncthreads();

    #define UGC(g, c) (*(const u64*)&Ugf[(g)][(c)][0])

    u64 ar[8], ai[8];

    // ---- Layer 1 (gates + cascade) closed-form into registers ----
    {
        const int ylow = (t ^ (t << 1)) & 255;   // low 8 bits of graymap(x)
        u64 pr = 0x3f8000003f800000ULL, pi = 0ULL;   // (1,1), (0,0)
        #pragma unroll
        for (int q = 0; q < 8; ++q) {
            const int bit = (ylow >> q) & 1;
            const u64 fr = bit ? UGC(q, 4) : UGC(q, 0);
            const u64 fi = bit ? UGC(q, 5) : UGC(q, 1);
            const u64 nr = ffma2(fneg2(pi), fi, fmul2(pr, fr));
            const u64 ni = ffma2(pi, fr, fmul2(pr, fi));
            pr = nr; pi = ni;
        }
        #pragma unroll
        for (int k = 0; k < 8; ++k) {
            const int y = graymap((k << 8) | t);
            u64 rr = pr, ri = pi;
            #pragma unroll
            for (int q = 8; q < NQ; ++q) {
                const int bit = (y >> q) & 1;
                const u64 fr = bit ? UGC(q, 4) : UGC(q, 0);
                const u64 fi = bit ? UGC(q, 5) : UGC(q, 1);
                const u64 nr = ffma2(fneg2(ri), fi, fmul2(rr, fr));
                const u64 ni = ffma2(ri, fr, fmul2(rr, fi));
                rr = nr; ri = ni;
            }
            ar[k] = rr; ai[k] = ri;
        }
    }

    // ---- Layer 2 ----

    // Local butterfly for gate g on local bit bq.
    #define LOCAL_GATE(g, bq)                                                 \
    {                                                                         \
        const u64 u00r = UGC(g, 0), u00i = UGC(g, 1);                         \
        const u64 u01r = UGC(g, 2), u01i = UGC(g, 3);                         \
        const u64 u10r = UGC(g, 4), u10i = UGC(g, 5);                         \
        const u64 u11r = UGC(g, 6), u11i = UGC(g, 7);                         \
        const u64 n00i = fneg2(u00i), n01i = fneg2(u01i);                     \
        const u64 n10i = fneg2(u10i), n11i = fneg2(u11i);                     \
        _Pragma("unroll")                                                     \
        for (int k = 0; k < 8; ++k) {                                         \
            if (k & (1 << (bq))) continue;                                    \
            const int k1 = k | (1 << (bq));                                   \
            const u64 a0r = ar[k],  a0i = ai[k];                              \
            const u64 a1r = ar[k1], a1i = ai[k1];                             \
            ar[k]  = ffma2(n01i, a1i, ffma2(u01r, a1r,                        \
                     ffma2(n00i, a0i, fmul2(u00r, a0r))));                    \
            ai[k]  = ffma2(u01i, a1r, ffma2(u01r, a1i,                        \
                     ffma2(u00i, a0r, fmul2(u00r, a0i))));                    \
            ar[k1] = ffma2(n11i, a1i, ffma2(u11r, a1r,                        \
                     ffma2(n10i, a0i, fmul2(u10r, a0r))));                    \
            ai[k1] = ffma2(u11i, a1r, ffma2(u11r, a1i,                        \
                     ffma2(u10i, a0r, fmul2(u10r, a0i))));                    \
        }                                                                     \
    }

    // Local gates: qubits 8,9,10 live in k bits 0,1,2.
    LOCAL_GATE(NQ + 8, 0)
    LOCAL_GATE(NQ + 9, 1)
    LOCAL_GATE(NQ + 10, 2)

    // Shuffle gates: qubits 0..4 live in lane bits 0..4.
    #pragma unroll
    for (int q = 0; q < 5; ++q) {
        const int g = NQ + q;
        const int bit = (lane >> q) & 1;
        const u64 csr = bit ? UGC(g, 6) : UGC(g, 0);
        const u64 csi = bit ? UGC(g, 7) : UGC(g, 1);
        const u64 cpr = bit ? UGC(g, 4) : UGC(g, 2);
        const u64 cpi = bit ? UGC(g, 5) : UGC(g, 3);
        const u64 ncsi = fneg2(csi), ncpi = fneg2(cpi);
        #pragma unroll
        for (int k = 0; k < 8; ++k) {
            const u64 prr = __shfl_xor_sync(0xffffffffu, ar[k], 1 << q);
            const u64 pri = __shfl_xor_sync(0xffffffffu, ai[k], 1 << q);
            const u64 nr = ffma2(ncpi, pri, ffma2(cpr, prr,
                           ffma2(ncsi, ai[k], fmul2(csr, ar[k]))));
            const u64 ni = ffma2(cpi, prr, ffma2(cpr, pri,
                           ffma2(csi, ar[k], fmul2(csr, ai[k]))));
            ar[k] = nr; ai[k] = ni;
        }
    }

    // Bit-swap transpose via smem: bits 5-7 <-> 8-10.
    #pragma unroll
    for (int k = 0; k < 8; ++k) {
        sre[(k << 8) | t] = ar[k];
        sim[(k << 8) | t] = ai[k];
    }
    __syncthreads();
    #pragma unroll
    for (int k = 0; k < 8; ++k) {
        const int y = (w << 8) | (k << 5) | lane;
        ar[k] = sre[y];
        ai[k] = sim[y];
    }
    // Thread now owns y = (w<<8)|(k<<5)|lane : qubits 5,6,7 are k bits 0,1,2.

    // Local gates: qubits 5,6,7.
    LOCAL_GATE(NQ + 5, 0)
    LOCAL_GATE(NQ + 6, 1)
    LOCAL_GATE(NQ + 7, 2)

    // Final CNOT cascade fused into output: re-only smem bounce.
    __syncthreads();                        // all transpose reads of sre done
    #pragma unroll
    for (int k = 0; k < 8; ++k)
        sre[(w << 8) | (k << 5) | lane] = ar[k];
    __syncthreads();

    float* ob0 = out + (long long)b0 * SDIM;
    float* ob1 = ob0 + SDIM;
    #pragma unroll
    for (int k = 0; k < 8; ++k) {
        const int x = t + (k << 8);
        float v0, v1;
        unpk(sre[graymap(x)], v0, v1);
        ob0[x] = v0;
        ob1[x] = v1;
    }
    #undef LOCAL_GATE
    #undef UGC
}

extern "C" void kernel_launch(void* const* d_in, const int* in_sizes, int n_in,
                              void* d_out, int out_size)
{
    const float* theta     = (const float*)d_in[0];
    const int*   positions = (const int*)d_in[1];
    float*       out       = (float*)d_out;

    const int batch = in_sizes[1];            // 4096
    pqc_kernel<<<batch / 2, NTHREADS>>>(theta, positions, out);
}

// round 4
// speedup vs baseline: 1.6832x; 1.6832x over previous
#include <cuda_runtime.h>

// Batched 11-qubit PQC simulation — scalar register-resident statevector.
//
//  * CNOT(q->q+1) cascade == permutation new[x] = old[(x ^ (x<<1)) & 2047].
//  * Layer 1 on |0> is a tensor product -> closed-form init into registers,
//    with the high-3-bit factor products shared via an 8-entry smem table.
//  * Layer 2: 11 commuting single-qubit gates applied where each bit lives:
//      qubits 8-10 : local (register) butterflies
//      qubits 0-4  : warp-shuffle butterflies
//      qubits 5-7  : one float2 smem bit-swap (5-7 <-> 8-10), then local
//                    butterflies (last gate computes real outputs only).
//  * Final cascade inverted (x = invgray(y)) and fused into direct STG.

#define NQ       11
#define NL       2
#define SDIM     2048
#define NTHREADS 256

__device__ __forceinline__ int graymap(int x) {
    return (x ^ (x << 1)) & (SDIM - 1);
}

// invgray: inverse of graymap (prefix-xor from LSB), 11-bit.
__host__ __device__ constexpr int invgray(int y) {
    int v = y;
    v ^= v << 1;
    v ^= v << 2;
    v ^= v << 4;
    v ^= v << 8;
    return v & (SDIM - 1);
}

__global__ __launch_bounds__(NTHREADS)
void pqc_kernel(const float* __restrict__ theta,
                const int*   __restrict__ positions,
                float*       __restrict__ out)
{
    __shared__ float2 st[SDIM];                 // 16 KB transpose buffer
    __shared__ float  Ug[NL * NQ][8];           // gate matrices
    __shared__ float2 Ftab[8];                  // layer-1 high-bit factor products

    const int b    = blockIdx.x;
    const int t    = threadIdx.x;
    const int lane = t & 31;
    const int w    = t >> 5;
    const int p    = positions[b];
    const float* th = theta + (long long)p * (NL * 3 * NQ);

    // ---- Gate matrices: U = Rz(g)*Ry(b)*Rx(a), half-angles ----
    if (t < NL * NQ) {
        const int l = t / NQ, q = t - l * NQ;
        const float a  = 0.5f * th[l * 3 * NQ + q * 3 + 0];
        const float bb = 0.5f * th[l * 3 * NQ + q * 3 + 1];
        const float g  = 0.5f * th[l * 3 * NQ + q * 3 + 2];
        float sa, ca, sb, cb, sg, cg;
        sincosf(a,  &sa, &ca);
        sincosf(bb, &sb, &cb);
        sincosf(g,  &sg, &cg);
        const float cbca = cb * ca, sbsa = sb * sa;
        const float sbca = sb * ca, cbsa = cb * sa;
        Ug[t][0] =  cg * cbca + sg * sbsa;   // u00.re
        Ug[t][1] =  cg * sbsa - sg * cbca;   // u00.im
        Ug[t][2] = -cg * sbca - sg * cbsa;   // u01.re
        Ug[t][3] = -cg * cbsa + sg * sbca;   // u01.im
        Ug[t][4] =  cg * sbca + sg * cbsa;   // u10.re
        Ug[t][5] =  sg * sbca - cg * cbsa;   // u10.im
        Ug[t][6] =  cg * cbca + sg * sbsa;   // u11.re
        Ug[t][7] =  sg * cbca - cg * sbsa;   // u11.im
    }
    __syncthreads();

    // ---- Layer-1 factor table: F[c] = f8(c0)*f9(c1)*f10(c2) ----
    if (t < 8) {
        float rr = 1.f, ri = 0.f;
        #pragma unroll
        for (int j = 0; j < 3; ++j) {
            const int q = 8 + j;
            const int bit = (t >> j) & 1;
            const float fr = bit ? Ug[q][4] : Ug[q][0];
            const float fi = bit ? Ug[q][5] : Ug[q][1];
            const float nr = rr * fr - ri * fi;
            const float ni = rr * fi + ri * fr;
            rr = nr; ri = ni;
        }
        Ftab[t] = make_float2(rr, ri);
    }
    __syncthreads();

    float ar[8], ai[8];

    // ---- Layer 1 (gates + cascade) closed-form into registers ----
    {
        const int ylow = (t ^ (t << 1)) & 255;   // low 8 bits of graymap(x)
        float pr = 1.f, pi = 0.f;
        #pragma unroll
        for (int q = 0; q < 8; ++q) {
            const float* u = Ug[q];
            const int bit = (ylow >> q) & 1;
            const float fr = bit ? u[4] : u[0];
            const float fi = bit ? u[5] : u[1];
            const float nr = pr * fr - pi * fi;
            const float ni = pr * fi + pi * fr;
            pr = nr; pi = ni;
        }
        const int t7 = (t >> 7) & 1;
        #pragma unroll
        for (int k = 0; k < 8; ++k) {
            const int k0 = k & 1, k1 = (k >> 1) & 1, k2 = (k >> 2) & 1;
            const int c = (k0 ^ t7) | ((k1 ^ k0) << 1) | ((k2 ^ k1) << 2);
            const float2 f = Ftab[c];
            ar[k] = pr * f.x - pi * f.y;
            ai[k] = pr * f.y + pi * f.x;
        }
    }

    // ---- Layer 2 ----

    // Local butterfly, both outputs.
    #define LOCAL_GATE(g, bq)                                                \
    {                                                                        \
        const float* u = Ug[g];                                              \
        const float u00r = u[0], u00i = u[1], u01r = u[2], u01i = u[3];      \
        const float u10r = u[4], u10i = u[5], u11r = u[6], u11i = u[7];      \
        _Pragma("unroll")                                                    \
        for (int k = 0; k < 8; ++k) {                                        \
            if (k & (1 << (bq))) continue;                                   \
            const int k1 = k | (1 << (bq));                                  \
            const float a0r = ar[k],  a0i = ai[k];                           \
            const float a1r = ar[k1], a1i = ai[k1];                          \
            ar[k]  = u00r*a0r - u00i*a0i + u01r*a1r - u01i*a1i;              \
            ai[k]  = u00r*a0i + u00i*a0r + u01r*a1i + u01i*a1r;              \
            ar[k1] = u10r*a0r - u10i*a0i + u11r*a1r - u11i*a1i;              \
            ai[k1] = u10r*a0i + u10i*a0r + u11r*a1i + u11i*a1r;              \
        }                                                                    \
    }

    // Local gates: qubits 8,9,10 live in k bits 0,1,2.
    LOCAL_GATE(NQ + 8, 0)
    LOCAL_GATE(NQ + 9, 1)
    LOCAL_GATE(NQ + 10, 2)

    // Shuffle gates: qubits 0..4 live in lane bits 0..4.
    #pragma unroll
    for (int q = 0; q < 5; ++q) {
        const float* u = Ug[NQ + q];
        const int bit = (lane >> q) & 1;
        const float csr = bit ? u[6] : u[0];
        const float csi = bit ? u[7] : u[1];
        const float cpr = bit ? u[4] : u[2];
        const float cpi = bit ? u[5] : u[3];
        #pragma unroll
        for (int k = 0; k < 8; ++k) {
            const float prr = __shfl_xor_sync(0xffffffffu, ar[k], 1 << q);
            const float pri = __shfl_xor_sync(0xffffffffu, ai[k], 1 << q);
            const float nr = csr*ar[k] - csi*ai[k] + cpr*prr - cpi*pri;
            const float ni = csr*ai[k] + csi*ar[k] + cpr*pri + cpi*prr;
            ar[k] = nr; ai[k] = ni;
        }
    }

    // Bit-swap transpose via float2 smem: bits 5-7 <-> 8-10.
    #pragma unroll
    for (int k = 0; k < 8; ++k)
        st[(k << 8) | t] = make_float2(ar[k], ai[k]);
    __syncthreads();
    #pragma unroll
    for (int k = 0; k < 8; ++k) {
        const float2 v = st[(w << 8) | (k << 5) | lane];
        ar[k] = v.x; ai[k] = v.y;
    }
    // Thread now owns y = (w<<8)|(k<<5)|lane : qubits 5,6,7 are k bits 0,1,2.

    // Local gates: qubits 5,6 (full), qubit 7 (real outputs only — imag dead).
    LOCAL_GATE(NQ + 5, 0)
    LOCAL_GATE(NQ + 6, 1)
    {
        const float* u = Ug[NQ + 7];
        const float u00r = u[0], u00i = u[1], u01r = u[2], u01i = u[3];
        const float u10r = u[4], u10i = u[5], u11r = u[6], u11i = u[7];
        #pragma unroll
        for (int k = 0; k < 4; ++k) {
            const int k1 = k | 4;
            const float a0r = ar[k],  a0i = ai[k];
            const float a1r = ar[k1], a1i = ai[k1];
            ar[k]  = u00r*a0r - u00i*a0i + u01r*a1r - u01i*a1i;
            ar[k1] = u10r*a0r - u10i*a0i + u11r*a1r - u11i*a1i;
        }
    }

    // ---- Final cascade: out[invgray(y)] = re(amp[y]), direct STG ----
    float* ob = out + (long long)b * SDIM;
    const int xbase = invgray((w << 8) | lane);
    #pragma unroll
    for (int k = 0; k < 8; ++k)
        ob[xbase ^ invgray(k << 5)] = ar[k];    // invgray(k<<5) is constexpr

    #undef LOCAL_GATE
}

extern "C" void kernel_launch(void* const* d_in, const int* in_sizes, int n_in,
                              void* d_out, int out_size)
{
    const float* theta     = (const float*)d_in[0];
    const int*   positions = (const int*)d_in[1];
    float*       out       = (float*)d_out;

    const int batch = in_sizes[1];            // 4096
    pqc_kernel<<<batch, NTHREADS>>>(theta, positions, out);
}

// round 5
// speedup vs baseline: 3.1634x; 1.8794x over previous
#include <cuda_runtime.h>

// Batched 11-qubit PQC simulation — transfer-matrix (MPS, bond dim 2) form.
//
// Derivation:
//   layer-1 on |0> then CNOT cascade:  amp1[z] = prod_q f_q(z_q ^ z_{q-1})
//     (f_q = column 0 of layer-1 gate q;  z_{-1} = 0)
//   layer-2 single-qubit gates:        amp2[y] = sum_z prod_q U2_q[y_q,z_q] amp1[z]
//   final cascade:                     out[w]  = Re( amp2[graymap(w)] )
// With c = graymap(w)  (c_q = w_q ^ w_{q-1}):
//   out[w] = Re( V0(c_0) · M_1(c_1) · ... · M_9(c_9) · G(c_10) )
//   M_q(c)[zp][zq] = U2_q[c, zq] * f_q(zq ^ zp)        (2x2 complex)
//   V0(c)[z0]      = U2_0[c, z0] * f_0(z0)             (row 2-vector)
//   G(c)[zp]       = U2_10[c,0]*f_10(zp) + U2_10[c,1]*f_10(1^zp)  (col 2-vector)
//
// Thread t owns w-bits 0..7 (= t); expands bits 8..10 as a 3-level tree.
// c-bits 0..7 depend only on t; c8 = k0^t7, c9 = k1^k0, c10 = k2^k1.

#define NQ       11
#define NL       2
#define SDIM     2048
#define NTHREADS 256

__global__ __launch_bounds__(NTHREADS)
void pqc_kernel(const float* __restrict__ theta,
                const int*   __restrict__ positions,
                float*       __restrict__ out)
{
    __shared__ float U1[NQ][8];        // layer-1 gates (need cols: u00,u10)
    __shared__ float U2[NQ][8];        // layer-2 gates
    __shared__ float V0[2][4];         // init row vector per c0
    __shared__ float Mt[9][2][8];      // M_q(c), q=1..9 -> Mt[q-1]
    __shared__ float G [2][4];         // closing col vector per c10

    const int b = blockIdx.x;
    const int t = threadIdx.x;
    const int p = positions[b];
    const float* th = theta + (long long)p * (NL * 3 * NQ);

    // ---- Stage 1: gate matrices U = Rz(g)*Ry(b)*Rx(a), half-angles ----
    if (t < NL * NQ) {
        const int l = t / NQ, q = t - l * NQ;
        const float a  = 0.5f * th[l * 3 * NQ + q * 3 + 0];
        const float bb = 0.5f * th[l * 3 * NQ + q * 3 + 1];
        const float g  = 0.5f * th[l * 3 * NQ + q * 3 + 2];
        float sa, ca, sb, cb, sg, cg;
        sincosf(a,  &sa, &ca);
        sincosf(bb, &sb, &cb);
        sincosf(g,  &sg, &cg);
        const float cbca = cb * ca, sbsa = sb * sa;
        const float sbca = sb * ca, cbsa = cb * sa;
        float* U = (l == 0) ? U1[q] : U2[q];
        U[0] =  cg * cbca + sg * sbsa;   // u00.re
        U[1] =  cg * sbsa - sg * cbca;   // u00.im
        U[2] = -cg * sbca - sg * cbsa;   // u01.re
        U[3] = -cg * cbsa + sg * sbca;   // u01.im
        U[4] =  cg * sbca + sg * cbsa;   // u10.re
        U[5] =  sg * sbca - cg * cbsa;   // u10.im
        U[6] =  cg * cbca + sg * sbsa;   // u11.re
        U[7] =  sg * cbca - cg * sbsa;   // u11.im
    }
    __syncthreads();

    // ---- Stage 2: transfer-matrix tables ----
    // f_q(bit):  re = bit ? U1[q][4] : U1[q][0],  im = bit ? U1[q][5] : U1[q][1]
    if (t < 18) {                       // Mt[q-1][c], q = 1..9
        const int q = 1 + (t >> 1);
        const int c = t & 1;
        float* M = Mt[q - 1][c];
        #pragma unroll
        for (int zp = 0; zp < 2; ++zp)
            #pragma unroll
            for (int zq = 0; zq < 2; ++zq) {
                const float ur = U2[q][(c * 2 + zq) * 2 + 0];
                const float ui = U2[q][(c * 2 + zq) * 2 + 1];
                const int fb = zq ^ zp;
                const float fr = fb ? U1[q][4] : U1[q][0];
                const float fi = fb ? U1[q][5] : U1[q][1];
                M[(zp * 2 + zq) * 2 + 0] = ur * fr - ui * fi;
                M[(zp * 2 + zq) * 2 + 1] = ur * fi + ui * fr;
            }
    } else if (t < 20) {                // V0[c]
        const int c = t - 18;
        #pragma unroll
        for (int z0 = 0; z0 < 2; ++z0) {
            const float ur = U2[0][(c * 2 + z0) * 2 + 0];
            const float ui = U2[0][(c * 2 + z0) * 2 + 1];
            const float fr = z0 ? U1[0][4] : U1[0][0];
            const float fi = z0 ? U1[0][5] : U1[0][1];
            V0[c][z0 * 2 + 0] = ur * fr - ui * fi;
            V0[c][z0 * 2 + 1] = ur * fi + ui * fr;
        }
    } else if (t < 22) {                // G[c]: g[zp] = sum_zq U2_10[c,zq] f_10(zq^zp)
        const int c = t - 20;
        #pragma unroll
        for (int zp = 0; zp < 2; ++zp) {
            float gr = 0.f, gi = 0.f;
            #pragma unroll
            for (int zq = 0; zq < 2; ++zq) {
                const float ur = U2[10][(c * 2 + zq) * 2 + 0];
                const float ui = U2[10][(c * 2 + zq) * 2 + 1];
                const int fb = zq ^ zp;
                const float fr = fb ? U1[10][4] : U1[10][0];
                const float fi = fb ? U1[10][5] : U1[10][1];
                gr += ur * fr - ui * fi;
                gi += ur * fi + ui * fr;
            }
            G[c][zp * 2 + 0] = gr;
            G[c][zp * 2 + 1] = gi;
        }
    }
    __syncthreads();

    // ---- Stage 3: per-thread chain over c-bits 0..7 ----
    const int c = (t ^ (t << 1)) & 255;     // graymap bits 0..7 (depend only on t)

    float v0r = V0[c & 1][0], v0i = V0[c & 1][1];
    float v1r = V0[c & 1][2], v1i = V0[c & 1][3];

    #pragma unroll
    for (int q = 1; q <= 7; ++q) {
        const float* M = Mt[q - 1][(c >> q) & 1];
        const float m00r = M[0], m00i = M[1], m01r = M[2], m01i = M[3];
        const float m10r = M[4], m10i = M[5], m11r = M[6], m11i = M[7];
        const float nr0 = v0r*m00r - v0i*m00i + v1r*m10r - v1i*m10i;
        const float ni0 = v0r*m00i + v0i*m00r + v1r*m10i + v1i*m10r;
        const float nr1 = v0r*m01r - v0i*m01i + v1r*m11r - v1i*m11i;
        const float ni1 = v0r*m01i + v0i*m01r + v1r*m11i + v1i*m11r;
        v0r = nr0; v0i = ni0; v1r = nr1; v1i = ni1;
    }

    // ---- Stage 4: expand bits 8..10 (tree) and store Re(leaf), coalesced ----
    float* ob = out + (long long)b * SDIM;
    const int t7 = (t >> 7) & 1;

    const float g0r0 = G[0][0], g0i0 = G[0][1], g0r1 = G[0][2], g0i1 = G[0][3];
    const float g1r0 = G[1][0], g1i0 = G[1][1], g1r1 = G[1][2], g1i1 = G[1][3];

    #pragma unroll
    for (int c8 = 0; c8 < 2; ++c8) {
        const float* M = Mt[7][c8];                 // q = 8
        const float a0r = v0r*M[0] - v0i*M[1] + v1r*M[4] - v1i*M[5];
        const float a0i = v0r*M[1] + v0i*M[0] + v1r*M[5] + v1i*M[4];
        const float a1r = v0r*M[2] - v0i*M[3] + v1r*M[6] - v1i*M[7];
        const float a1i = v0r*M[3] + v0i*M[2] + v1r*M[7] + v1i*M[6];
        const int k0 = c8 ^ t7;

        #pragma unroll
        for (int c9 = 0; c9 < 2; ++c9) {
            const float* N = Mt[8][c9];             // q = 9
            const float b0r = a0r*N[0] - a0i*N[1] + a1r*N[4] - a1i*N[5];
            const float b0i = a0r*N[1] + a0i*N[0] + a1r*N[5] + a1i*N[4];
            const float b1r = a0r*N[2] - a0i*N[3] + a1r*N[6] - a1i*N[7];
            const float b1i = a0r*N[3] + a0i*N[2] + a1r*N[7] + a1i*N[6];
            const int k1 = c9 ^ k0;

            // c10 = 0:
            {
                const int k2 = 0 ^ k1;
                const float val = b0r*g0r0 - b0i*g0i0 + b1r*g0r1 - b1i*g0i1;
                ob[t + ((k0 | (k1 << 1) | (k2 << 2)) << 8)] = val;
            }
            // c10 = 1:
            {
                const int k2 = 1 ^ k1;
                const float val = b0r*g1r0 - b0i*g1i0 + b1r*g1r1 - b1i*g1i1;
                ob[t + ((k0 | (k1 << 1) | (k2 << 2)) << 8)] = val;
            }
        }
    }
}

extern "C" void kernel_launch(void* const* d_in, const int* in_sizes, int n_in,
                              void* d_out, int out_size)
{
    const float* theta     = (const float*)d_in[0];
    const int*   positions = (const int*)d_in[1];
    float*       out       = (float*)d_out;

    const int batch = in_sizes[1];            // 4096
    pqc_kernel<<<batch, NTHREADS>>>(theta, positions, out);
}

// round 6
// speedup vs baseline: 4.4752x; 1.4147x over previous
#include <cuda_runtime.h>

// Batched 11-qubit PQC — transfer-matrix form with group-folded tables.
//
//   out[w] = Re( V0(c0)·M1(c1)···M9(c9)·G(c10) ),  c = graymap(w)
// Precompute per CTA:
//   T1[c0..c3] = V0·M1·M2·M3            (16 row 2-vectors)
//   T2[c4..c7] = M4·M5·M6·M7            (16 2x2 matrices)
//   W[c8,c9,c10] = M8·(M9·G)            (8 col 2-vectors)
// Per thread (t = w bits 0..7):
//   v2 = T1[c&15]·T2[c>>4]; 8 leaves: out = Re(v2·W[cc]), coalesced STG.

#define NQ       11
#define NL       2
#define SDIM     2048
#define NTHREADS 256

struct C2 { float r, i; };
__device__ __forceinline__ C2 cmul(C2 a, C2 b) {
    return { a.r*b.r - a.i*b.i, a.r*b.i + a.i*b.r };
}
__device__ __forceinline__ C2 cfma(C2 a, C2 b, C2 c) {   // a*b + c
    return { fmaf(a.r, b.r, fmaf(-a.i, b.i, c.r)),
             fmaf(a.r, b.i, fmaf( a.i, b.r, c.i)) };
}

__global__ __launch_bounds__(NTHREADS)
void pqc_kernel(const float* __restrict__ theta,
                const int*   __restrict__ positions,
                float*       __restrict__ out)
{
    __shared__ float U1[NQ][8];          // layer-1 gates
    __shared__ float U2[NQ][8];          // layer-2 gates
    __shared__ float V01[4][4];          // V0(c0)·M1(c1)           row vec
    __shared__ float P23[4][8];          // M2(c2)·M3(c3)           matrix
    __shared__ float P45[4][8];          // M4·M5
    __shared__ float P67[4][8];          // M6·M7
    __shared__ float P910[4][4];         // M9(c9)·G(c10)           col vec
    __shared__ float4 T1[16];            // V0·M1·M2·M3             row vec
    __shared__ float4 T2[16][2];         // M4·M5·M6·M7  (2 rows)
    __shared__ float4 W[8];              // M8·M9·G                 col vec

    const int b = blockIdx.x;
    const int t = threadIdx.x;
    const int p = positions[b];
    const float* th = theta + (long long)p * (NL * 3 * NQ);

    // ---- Stage A: gate matrices U = Rz(g)*Ry(b)*Rx(a), half-angles ----
    if (t < NL * NQ) {
        const int l = t / NQ, q = t - l * NQ;
        const float a  = 0.5f * th[l * 3 * NQ + q * 3 + 0];
        const float bb = 0.5f * th[l * 3 * NQ + q * 3 + 1];
        const float g  = 0.5f * th[l * 3 * NQ + q * 3 + 2];
        float sa, ca, sb, cb, sg, cg;
        sincosf(a,  &sa, &ca);
        sincosf(bb, &sb, &cb);
        sincosf(g,  &sg, &cg);
        const float cbca = cb * ca, sbsa = sb * sa;
        const float sbca = sb * ca, cbsa = cb * sa;
        float* U = (l == 0) ? U1[q] : U2[q];
        U[0] =  cg * cbca + sg * sbsa;   // u00.re
        U[1] =  cg * sbsa - sg * cbca;   // u00.im
        U[2] = -cg * sbca - sg * cbsa;   // u01.re
        U[3] = -cg * cbsa + sg * sbca;   // u01.im
        U[4] =  cg * sbca + sg * cbsa;   // u10.re
        U[5] =  sg * sbca - cg * cbsa;   // u10.im
        U[6] =  cg * cbca + sg * sbsa;   // u11.re
        U[7] =  sg * cbca - cg * sbsa;   // u11.im
    }
    __syncthreads();

    // buildM: M_q(c)[zp][zq] = U2_q[c,zq] * f_q(zq^zp),
    //         f_q(bit) = (U1[q][4],U1[q][5]) if bit else (U1[q][0],U1[q][1])
    #define BUILD_M(m, U1q, U2q, c)                            \
        {                                                      \
            const C2 u0 = { (U2q)[(c)*4+0], (U2q)[(c)*4+1] };  \
            const C2 u1 = { (U2q)[(c)*4+2], (U2q)[(c)*4+3] };  \
            const C2 f0 = { (U1q)[0], (U1q)[1] };              \
            const C2 f1 = { (U1q)[4], (U1q)[5] };              \
            m[0] = cmul(u0, f0);  /* zp0,zq0 */                \
            m[1] = cmul(u1, f1);  /* zp0,zq1 */                \
            m[2] = cmul(u0, f1);  /* zp1,zq0 */                \
            m[3] = cmul(u1, f0);  /* zp1,zq1 */                \
        }

    // ---- Stage B1: pair products ----
    if (t < 4) {                         // V01[c0,c1] = V0(c0)·M1(c1)
        const int c0 = t & 1, c1 = t >> 1;
        const C2 u0 = { U2[0][c0*4+0], U2[0][c0*4+1] };
        const C2 u1 = { U2[0][c0*4+2], U2[0][c0*4+3] };
        const C2 f0 = { U1[0][0], U1[0][1] };
        const C2 f1 = { U1[0][4], U1[0][5] };
        const C2 v0 = cmul(u0, f0);
        const C2 v1 = cmul(u1, f1);
        C2 m[4]; BUILD_M(m, U1[1], U2[1], c1);
        const C2 r0 = cfma(v0, m[0], cmul(v1, m[2]));
        const C2 r1 = cfma(v0, m[1], cmul(v1, m[3]));
        V01[t][0] = r0.r; V01[t][1] = r0.i;
        V01[t][2] = r1.r; V01[t][3] = r1.i;
    } else if (t < 16) {                 // P23 / P45 / P67
        const int grp = (t - 4) >> 2;    // 0,1,2
        const int idx = (t - 4) & 3;
        const int qa = 2 + grp * 2, qb = qa + 1;
        const int ca = idx & 1, cb = idx >> 1;
        C2 A[4], B[4];
        BUILD_M(A, U1[qa], U2[qa], ca);
        BUILD_M(B, U1[qb], U2[qb], cb);
        float* o = (grp == 0) ? P23[idx] : (grp == 1) ? P45[idx] : P67[idx];
        const C2 c00 = cfma(A[0], B[0], cmul(A[1], B[2]));
        const C2 c01 = cfma(A[0], B[1], cmul(A[1], B[3]));
        const C2 c10 = cfma(A[2], B[0], cmul(A[3], B[2]));
        const C2 c11 = cfma(A[2], B[1], cmul(A[3], B[3]));
        o[0] = c00.r; o[1] = c00.i; o[2] = c01.r; o[3] = c01.i;
        o[4] = c10.r; o[5] = c10.i; o[6] = c11.r; o[7] = c11.i;
    } else if (t < 20) {                 // P910[c9,c10] = M9(c9)·G(c10)
        const int idx = t - 16;
        const int c9 = idx & 1, c10 = idx >> 1;
        const C2 u0 = { U2[10][c10*4+0], U2[10][c10*4+1] };
        const C2 u1 = { U2[10][c10*4+2], U2[10][c10*4+3] };
        const C2 f0 = { U1[10][0], U1[10][1] };
        const C2 f1 = { U1[10][4], U1[10][5] };
        const C2 g0 = cfma(u0, f0, cmul(u1, f1));   // G[zp=0]
        const C2 g1 = cfma(u0, f1, cmul(u1, f0));   // G[zp=1]
        C2 m[4]; BUILD_M(m, U1[9], U2[9], c9);
        const C2 p0 = cfma(m[0], g0, cmul(m[1], g1));
        const C2 p1 = cfma(m[2], g0, cmul(m[3], g1));
        P910[idx][0] = p0.r; P910[idx][1] = p0.i;
        P910[idx][2] = p1.r; P910[idx][3] = p1.i;
    }
    __syncthreads();

    // ---- Stage B2: group products (spread over 3 warps) ----
    if (t < 16) {                        // T1[i] = V01[i&3] · P23[i>>2]
        const float* a = V01[t & 3];
        const float* Bm = P23[t >> 2];
        const C2 a0 = { a[0], a[1] }, a1 = { a[2], a[3] };
        const C2 B00 = { Bm[0], Bm[1] }, B01 = { Bm[2], Bm[3] };
        const C2 B10 = { Bm[4], Bm[5] }, B11 = { Bm[6], Bm[7] };
        const C2 r0 = cfma(a0, B00, cmul(a1, B10));
        const C2 r1 = cfma(a0, B01, cmul(a1, B11));
        T1[t] = make_float4(r0.r, r0.i, r1.r, r1.i);
    } else if (t >= 32 && t < 48) {      // T2[i] = P45[i&3] · P67[i>>2]
        const int i = t - 32;
        const float* Am = P45[i & 3];
        const float* Bm = P67[i >> 2];
        const C2 A00 = { Am[0], Am[1] }, A01 = { Am[2], Am[3] };
        const C2 A10 = { Am[4], Am[5] }, A11 = { Am[6], Am[7] };
        const C2 B00 = { Bm[0], Bm[1] }, B01 = { Bm[2], Bm[3] };
        const C2 B10 = { Bm[4], Bm[5] }, B11 = { Bm[6], Bm[7] };
        const C2 c00 = cfma(A00, B00, cmul(A01, B10));
        const C2 c01 = cfma(A00, B01, cmul(A01, B11));
        const C2 c10 = cfma(A10, B00, cmul(A11, B10));
        const C2 c11 = cfma(A10, B01, cmul(A11, B11));
        T2[i][0] = make_float4(c00.r, c00.i, c01.r, c01.i);
        T2[i][1] = make_float4(c10.r, c10.i, c11.r, c11.i);
    } else if (t >= 64 && t < 72) {      // W[i] = M8(c8) · P910[(c9,c10)]
        const int i = t - 64;
        const int c8 = i & 1;
        const float* pv = P910[i >> 1];
        const C2 p0 = { pv[0], pv[1] }, p1 = { pv[2], pv[3] };
        C2 m[4]; BUILD_M(m, U1[8], U2[8], c8);
        const C2 w0 = cfma(m[0], p0, cmul(m[1], p1));
        const C2 w1 = cfma(m[2], p0, cmul(m[3], p1));
        W[i] = make_float4(w0.r, w0.i, w1.r, w1.i);
    }
    __syncthreads();

    // ---- Main: per-thread fold + 8 leaves ----
    const int c  = (t ^ (t << 1)) & 255;   // graymap bits 0..7
    const int t7 = (t >> 7) & 1;

    const float4 a  = T1[c & 15];
    const float4 B0 = T2[c >> 4][0];
    const float4 B1 = T2[c >> 4][1];
    const C2 a0 = { a.x, a.y }, a1 = { a.z, a.w };
    const C2 v20 = cfma(a0, { B0.x, B0.y }, cmul(a1, { B1.x, B1.y }));
    const C2 v21 = cfma(a0, { B0.z, B0.w }, cmul(a1, { B1.z, B1.w }));

    float* ob = out + (long long)b * SDIM;
    #pragma unroll
    for (int cc = 0; cc < 8; ++cc) {
        const int c8 = cc & 1, c9 = (cc >> 1) & 1, c10 = cc >> 2;
        const int k0 = c8 ^ t7;
        const int k1 = c9 ^ k0;
        const int k2 = c10 ^ k1;
        const float4 w = W[cc];
        const float val = v20.r*w.x - v20.i*w.y + v21.r*w.z - v21.i*w.w;
        ob[t + ((k0 | (k1 << 1) | (k2 << 2)) << 8)] = val;
    }
    #undef BUILD_M
}

extern "C" void kernel_launch(void* const* d_in, const int* in_sizes, int n_in,
                              void* d_out, int out_size)
{
    const float* theta     = (const float*)d_in[0];
    const int*   positions = (const int*)d_in[1];
    float*       out       = (float*)d_out;

    const int batch = in_sizes[1];            // 4096
    pqc_kernel<<<batch, NTHREADS>>>(theta, positions, out);
}

// round 7
// speedup vs baseline: 5.1800x; 1.1575x over previous
#include <cuda_runtime.h>

// Batched 11-qubit PQC — transfer-matrix form, group-folded tables,
// 8 batch elements per CTA to amortize table-build setup.
//
//   out[w] = Re( V0(c0)·M1(c1)···M9(c9)·G(c10) ),  c = graymap(w)
// Per CTA (8 batches in parallel):
//   T1[c0..c3] = V0·M1·M2·M3            (16 row 2-vectors)
//   T2[c4..c7] = M4·M5·M6·M7            (16 2x2 matrices)
//   W[c8,c9,c10] = M8·(M9·G)            (8 col 2-vectors)
// Main, per thread per batch (t = w bits 0..7):
//   v2 = T1[c&15]·T2[c>>4]; 8 leaves: out = Re(v2·W[cc]), coalesced STG,
//   cc = ((k^(k<<1))&7) ^ t7  (warp-uniform -> smem broadcast).

#define NQ       11
#define NL       2
#define SDIM     2048
#define NTHREADS 256
#define NB       8            // batch elements per CTA

struct C2 { float r, i; };
__device__ __forceinline__ C2 cmul(C2 a, C2 b) {
    return { a.r*b.r - a.i*b.i, a.r*b.i + a.i*b.r };
}
__device__ __forceinline__ C2 cfma(C2 a, C2 b, C2 c) {   // a*b + c
    return { fmaf(a.r, b.r, fmaf(-a.i, b.i, c.r)),
             fmaf(a.r, b.i, fmaf( a.i, b.r, c.i)) };
}

__global__ __launch_bounds__(NTHREADS)
void pqc_kernel(const float* __restrict__ theta,
                const int*   __restrict__ positions,
                float*       __restrict__ out,
                int batch)
{
    __shared__ float  U1[NB][NQ][8];     // layer-1 gates
    __shared__ float  U2[NB][NQ][8];     // layer-2 gates
    __shared__ float  V01[NB][4][4];     // V0(c0)·M1(c1)     row vec
    __shared__ float  P23[NB][4][8];     // M2·M3             matrix
    __shared__ float  P45[NB][4][8];     // M4·M5
    __shared__ float  P67[NB][4][8];     // M6·M7
    __shared__ float  P910[NB][4][4];    // M9(c9)·G(c10)     col vec
    __shared__ float4 T1s[NB][16];       // V0·M1·M2·M3       row vec
    __shared__ float4 T2s[NB][16][2];    // M4·M5·M6·M7  (2 rows)
    __shared__ float4 Ws[NB][8];         // M8·M9·G           col vec

    const int t  = threadIdx.x;
    const int b0 = blockIdx.x * NB;

    // ---- Stage A: gate matrices U = Rz(g)*Ry(b)*Rx(a), half-angles ----
    if (t < NB * NL * NQ) {              // 176 threads
        const int j = t / (NL * NQ);
        const int g = t - j * (NL * NQ);
        const int l = (g >= NQ) ? 1 : 0;
        const int q = g - l * NQ;
        const int bidx = min(b0 + j, batch - 1);
        const int p = positions[bidx];
        const float* th = theta + (long long)p * (NL * 3 * NQ) + l * 3 * NQ + q * 3;
        const float a  = 0.5f * th[0];
        const float bb = 0.5f * th[1];
        const float gg = 0.5f * th[2];
        float sa, ca, sb, cb, sg, cg;
        sincosf(a,  &sa, &ca);
        sincosf(bb, &sb, &cb);
        sincosf(gg, &sg, &cg);
        const float cbca = cb * ca, sbsa = sb * sa;
        const float sbca = sb * ca, cbsa = cb * sa;
        float* U = l ? U2[j][q] : U1[j][q];
        U[0] =  cg * cbca + sg * sbsa;   // u00.re
        U[1] =  cg * sbsa - sg * cbca;   // u00.im
        U[2] = -cg * sbca - sg * cbsa;   // u01.re
        U[3] = -cg * cbsa + sg * sbca;   // u01.im
        U[4] =  cg * sbca + sg * cbsa;   // u10.re
        U[5] =  sg * sbca - cg * cbsa;   // u10.im
        U[6] =  cg * cbca + sg * sbsa;   // u11.re
        U[7] =  sg * cbca - cg * sbsa;   // u11.im
    }
    __syncthreads();

    // M_q(c)[zp][zq] = U2_q[c,zq] * f_q(zq^zp);  f_q from column 0 of U1_q.
    #define BUILD_M(m, U1q, U2q, c)                            \
        {                                                      \
            const C2 u0 = { (U2q)[(c)*4+0], (U2q)[(c)*4+1] };  \
            const C2 u1 = { (U2q)[(c)*4+2], (U2q)[(c)*4+3] };  \
            const C2 f0 = { (U1q)[0], (U1q)[1] };              \
            const C2 f1 = { (U1q)[4], (U1q)[5] };              \
            m[0] = cmul(u0, f0);  /* zp0,zq0 */                \
            m[1] = cmul(u1, f1);  /* zp0,zq1 */                \
            m[2] = cmul(u0, f1);  /* zp1,zq0 */                \
            m[3] = cmul(u1, f0);  /* zp1,zq1 */                \
        }

    // ---- Stage B1: pair products (8 batches x 20 items = 160 threads) ----
    if (t < NB * 20) {
        const int j = t / 20;
        const int i = t - j * 20;
        if (i < 4) {                     // V01[c0,c1] = V0(c0)·M1(c1)
            const int c0 = i & 1, c1 = i >> 1;
            const C2 u0 = { U2[j][0][c0*4+0], U2[j][0][c0*4+1] };
            const C2 u1 = { U2[j][0][c0*4+2], U2[j][0][c0*4+3] };
            const C2 f0 = { U1[j][0][0], U1[j][0][1] };
            const C2 f1 = { U1[j][0][4], U1[j][0][5] };
            const C2 v0 = cmul(u0, f0);
            const C2 v1 = cmul(u1, f1);
            C2 m[4]; BUILD_M(m, U1[j][1], U2[j][1], c1);
            const C2 r0 = cfma(v0, m[0], cmul(v1, m[2]));
            const C2 r1 = cfma(v0, m[1], cmul(v1, m[3]));
            V01[j][i][0] = r0.r; V01[j][i][1] = r0.i;
            V01[j][i][2] = r1.r; V01[j][i][3] = r1.i;
        } else if (i < 16) {             // P23 / P45 / P67
            const int grp = (i - 4) >> 2;
            const int idx = (i - 4) & 3;
            const int qa = 2 + grp * 2, qb = qa + 1;
            const int ca = idx & 1, cb = idx >> 1;
            C2 A[4], B[4];
            BUILD_M(A, U1[j][qa], U2[j][qa], ca);
            BUILD_M(B, U1[j][qb], U2[j][qb], cb);
            float* o = (grp == 0) ? P23[j][idx] : (grp == 1) ? P45[j][idx] : P67[j][idx];
            const C2 c00 = cfma(A[0], B[0], cmul(A[1], B[2]));
            const C2 c01 = cfma(A[0], B[1], cmul(A[1], B[3]));
            const C2 c10 = cfma(A[2], B[0], cmul(A[3], B[2]));
            const C2 c11 = cfma(A[2], B[1], cmul(A[3], B[3]));
            o[0] = c00.r; o[1] = c00.i; o[2] = c01.r; o[3] = c01.i;
            o[4] = c10.r; o[5] = c10.i; o[6] = c11.r; o[7] = c11.i;
        } else {                         // P910[c9,c10] = M9(c9)·G(c10)
            const int idx = i - 16;
            const int c9 = idx & 1, c10 = idx >> 1;
            const C2 u0 = { U2[j][10][c10*4+0], U2[j][10][c10*4+1] };
            const C2 u1 = { U2[j][10][c10*4+2], U2[j][10][c10*4+3] };
            const C2 f0 = { U1[j][10][0], U1[j][10][1] };
            const C2 f1 = { U1[j][10][4], U1[j][10][5] };
            const C2 g0 = cfma(u0, f0, cmul(u1, f1));   // G[zp=0]
            const C2 g1 = cfma(u0, f1, cmul(u1, f0));   // G[zp=1]
            C2 m[4]; BUILD_M(m, U1[j][9], U2[j][9], c9);
            const C2 p0 = cfma(m[0], g0, cmul(m[1], g1));
            const C2 p1 = cfma(m[2], g0, cmul(m[3], g1));
            P910[j][idx][0] = p0.r; P910[j][idx][1] = p0.i;
            P910[j][idx][2] = p1.r; P910[j][idx][3] = p1.i;
        }
    }
    __syncthreads();

    // ---- Stage B2: group products ----
    {   // all 256 threads: one T item each (8 batches x 32)
        const int j = t >> 5;
        const int i = t & 31;
        if (i < 16) {                    // T1[i] = V01[i&3] · P23[i>>2]
            const float* a  = V01[j][i & 3];
            const float* Bm = P23[j][i >> 2];
            const C2 a0 = { a[0], a[1] }, a1 = { a[2], a[3] };
            const C2 B00 = { Bm[0], Bm[1] }, B01 = { Bm[2], Bm[3] };
            const C2 B10 = { Bm[4], Bm[5] }, B11 = { Bm[6], Bm[7] };
            const C2 r0 = cfma(a0, B00, cmul(a1, B10));
            const C2 r1 = cfma(a0, B01, cmul(a1, B11));
            T1s[j][i] = make_float4(r0.r, r0.i, r1.r, r1.i);
        } else {                         // T2[i-16] = P45 · P67
            const int ii = i - 16;
            const float* Am = P45[j][ii & 3];
            const float* Bm = P67[j][ii >> 2];
            const C2 A00 = { Am[0], Am[1] }, A01 = { Am[2], Am[3] };
            const C2 A10 = { Am[4], Am[5] }, A11 = { Am[6], Am[7] };
            const C2 B00 = { Bm[0], Bm[1] }, B01 = { Bm[2], Bm[3] };
            const C2 B10 = { Bm[4], Bm[5] }, B11 = { Bm[6], Bm[7] };
            const C2 c00 = cfma(A00, B00, cmul(A01, B10));
            const C2 c01 = cfma(A00, B01, cmul(A01, B11));
            const C2 c10 = cfma(A10, B00, cmul(A11, B10));
            const C2 c11 = cfma(A10, B01, cmul(A11, B11));
            T2s[j][ii][0] = make_float4(c00.r, c00.i, c01.r, c01.i);
            T2s[j][ii][1] = make_float4(c10.r, c10.i, c11.r, c11.i);
        }
    }
    if (t < NB * 8) {                    // W[i] = M8(c8) · P910  (64 threads)
        const int j = t >> 3;
        const int i = t & 7;
        const int c8 = i & 1;
        const float* pv = P910[j][i >> 1];
        const C2 p0 = { pv[0], pv[1] }, p1 = { pv[2], pv[3] };
        C2 m[4]; BUILD_M(m, U1[j][8], U2[j][8], c8);
        const C2 w0 = cfma(m[0], p0, cmul(m[1], p1));
        const C2 w1 = cfma(m[2], p0, cmul(m[3], p1));
        Ws[j][i] = make_float4(w0.r, w0.i, w1.r, w1.i);
    }
    __syncthreads();

    // ---- Main: per-thread fold + 8 leaves, for each of the 8 batches ----
    const int c  = (t ^ (t << 1)) & 255;   // graymap bits 0..7
    const int t7 = (t >> 7) & 1;

    #pragma unroll
    for (int j = 0; j < NB; ++j) {
        if (b0 + j >= batch) break;
        const float4 a  = T1s[j][c & 15];
        const float4 B0 = T2s[j][c >> 4][0];
        const float4 B1 = T2s[j][c >> 4][1];
        const C2 a0 = { a.x, a.y }, a1 = { a.z, a.w };
        const C2 v20 = cfma(a0, { B0.x, B0.y }, cmul(a1, { B1.x, B1.y }));
        const C2 v21 = cfma(a0, { B0.z, B0.w }, cmul(a1, { B1.z, B1.w }));

        float* ob = out + (long long)(b0 + j) * SDIM + t;
        #pragma unroll
        for (int k = 0; k < 8; ++k) {
            const int cc = (((k ^ (k << 1)) & 7) ^ t7);
            const float4 w = Ws[j][cc];
            const float val = v20.r*w.x - v20.i*w.y + v21.r*w.z - v21.i*w.w;
            ob[k << 8] = val;
        }
    }
    #undef BUILD_M
}

extern "C" void kernel_launch(void* const* d_in, const int* in_sizes, int n_in,
                              void* d_out, int out_size)
{
    const float* theta     = (const float*)d_in[0];
    const int*   positions = (const int*)d_in[1];
    float*       out       = (float*)d_out;

    const int batch = in_sizes[1];            // 4096
    const int blocks = (batch + NB - 1) / NB; // 512
    pqc_kernel<<<blocks, NTHREADS>>>(theta, positions, out, batch);
}